// round 8
// baseline (speedup 1.0000x reference)
#include <cuda_runtime.h>
#include <cuda_fp16.h>
#include <cstdint>

// Problem constants (fixed shapes per reference)
#define NN 100000
#define EE 1600000
#define HID 64

// ---------------- device scratch (no allocations allowed) ----------------
__device__ int   g_cnt[NN];        // in-degree; zero at first call (BSS), reset by agg_fc
__device__ float g_dinv[NN];
__device__ int   g_rowptr[NN + 1];
__device__ int   g_fill[NN];
__device__ int   g_col[EE];
__device__ __align__(16) float   g_h1[(size_t)NN * HID];   // layer transform out (fp32)
__device__ __align__(16) __half2 g_hh[(size_t)NN * HID/2]; // fp16 dinv-premult copy for gathers
__device__ __align__(16) float   g_ha[(size_t)NN * HID];   // post-aggregation activations

// per-warp edge dtype detection (int64 vs int32), no global state
__device__ __forceinline__ bool warp_is64(const void* ei) {
    int lane = threadIdx.x & 31;
    const long long* p = (const long long*)ei;
    long long v0 = p[lane * 2];
    long long v1 = p[lane * 2 + 1];
    bool ok = (v0 >= 0) && (v0 < NN) && (v1 >= 0) && (v1 < NN);
    return __all_sync(0xffffffffu, ok);
}

// ---------------- kernel 1: gemm1 (raw, no dinv) fused with degree count ----------------
// All blocks do a grid-stride degree-count chunk; blocks with a valid tile also
// compute a 128x64 gemm tile of h1 = x @ W1 (raw fp32). Phases are independent.
__global__ __launch_bounds__(256) void gemm1_count_kernel(const float* __restrict__ A,
                                                          const float* __restrict__ B,
                                                          float* __restrict__ C, int M,
                                                          const void* ei, int E) {
    // --- count phase ---
    bool is64 = warp_is64(ei);
    for (int e = blockIdx.x * blockDim.x + threadIdx.x; e < E;
         e += gridDim.x * blockDim.x) {
        int dst = is64 ? (int)((const long long*)ei)[E + e] : ((const int*)ei)[E + e];
        atomicAdd(&g_cnt[dst], 1);
    }

    // --- gemm phase (K=256) ---
    const int row0 = blockIdx.x * 128;
    if (row0 >= M) return;
    __shared__ float xs[128][32];
    __shared__ float ws[32][64];
    const int tid = threadIdx.x;
    const int tx = tid & 15, ty = tid >> 4;
    const int K = 256;
    float acc[8][4] = {};

    for (int kt = 0; kt < K; kt += 32) {
        #pragma unroll
        for (int it = 0; it < 4; it++) {
            int idx = tid + it * 256;
            int r = idx >> 3, c4 = idx & 7;
            int grow = row0 + r;
            float4 v = make_float4(0.f, 0.f, 0.f, 0.f);
            if (grow < M) v = *(const float4*)&A[(size_t)grow * K + kt + c4 * 4];
            *(float4*)&xs[r][c4 * 4] = v;
        }
        #pragma unroll
        for (int it = 0; it < 2; it++) {
            int idx = tid + it * 256;
            int kk = idx >> 4, c4 = idx & 15;
            *(float4*)&ws[kk][c4 * 4] = *(const float4*)&B[(size_t)(kt + kk) * 64 + c4 * 4];
        }
        __syncthreads();
        #pragma unroll
        for (int k = 0; k < 32; k++) {
            float4 b = *(float4*)&ws[k][tx * 4];
            #pragma unroll
            for (int r = 0; r < 8; r++) {
                float a = xs[ty * 8 + r][k];
                acc[r][0] += a * b.x;
                acc[r][1] += a * b.y;
                acc[r][2] += a * b.z;
                acc[r][3] += a * b.w;
            }
        }
        __syncthreads();
    }
    #pragma unroll
    for (int r = 0; r < 8; r++) {
        int grow = row0 + ty * 8 + r;
        if (grow < M)
            *(float4*)&C[(size_t)grow * 64 + tx * 4] =
                make_float4(acc[r][0], acc[r][1], acc[r][2], acc[r][3]);
    }
}

// ---------------- kernel 2: scan -> rowptr, dinv, fill init ----------------
__global__ __launch_bounds__(1024) void scan_kernel(int n) {
    const int tid = threadIdx.x;
    __shared__ int wsum[32];
    __shared__ int carry;
    if (tid == 0) carry = 0;
    __syncthreads();
    const int4* c4 = (const int4*)g_cnt;
    int nv4 = n >> 2;
    for (int base = 0; base < nv4; base += 1024) {
        int idx = base + tid;
        int4 v = make_int4(0, 0, 0, 0);
        if (idx < nv4) v = c4[idx];
        int s = v.x + v.y + v.z + v.w;
        int x = s;
        #pragma unroll
        for (int o = 1; o < 32; o <<= 1) {
            int y = __shfl_up_sync(0xffffffffu, x, o);
            if ((tid & 31) >= o) x += y;
        }
        if ((tid & 31) == 31) wsum[tid >> 5] = x;
        __syncthreads();
        if (tid < 32) {
            int w = wsum[tid];
            #pragma unroll
            for (int o = 1; o < 32; o <<= 1) {
                int y = __shfl_up_sync(0xffffffffu, w, o);
                if (tid >= o) w += y;
            }
            wsum[tid] = w;
        }
        __syncthreads();
        int excl = x - s + ((tid >= 32) ? wsum[(tid >> 5) - 1] : 0) + carry;
        if (idx < nv4) {
            g_rowptr[idx * 4 + 0] = excl;
            g_rowptr[idx * 4 + 1] = excl + v.x;
            g_rowptr[idx * 4 + 2] = excl + v.x + v.y;
            g_rowptr[idx * 4 + 3] = excl + v.x + v.y + v.z;
            *(float4*)&g_dinv[idx * 4] = make_float4(
                rsqrtf((float)(v.x + 1)), rsqrtf((float)(v.y + 1)),
                rsqrtf((float)(v.z + 1)), rsqrtf((float)(v.w + 1)));
            *(int4*)&g_fill[idx * 4] = make_int4(0, 0, 0, 0);
        }
        __syncthreads();
        if (tid == 1023) carry = excl + s;
        __syncthreads();
    }
    if (tid == 0) g_rowptr[n] = carry;
}

// ---------------- kernel 3: CSR scatter fused with fp16 convert ----------------
// Blocks [0, nbScat): scatter edges into g_col. Blocks [nbScat, ...): convert
// hh[i] = fp16(dinv[i] * h1[i]) (independent work, fused to save a launch).
__global__ __launch_bounds__(256) void scatter_convert_kernel(const void* ei, int E,
                                                              int nbScat,
                                                              const float2* __restrict__ h1,
                                                              __half2* __restrict__ hh,
                                                              int n) {
    if ((int)blockIdx.x < nbScat) {
        bool is64 = warp_is64(ei);
        int e = blockIdx.x * blockDim.x + threadIdx.x;
        if (e >= E) return;
        int src, dst;
        if (is64) {
            src = (int)((const long long*)ei)[e];
            dst = (int)((const long long*)ei)[E + e];
        } else {
            src = ((const int*)ei)[e];
            dst = ((const int*)ei)[E + e];
        }
        int pos = g_rowptr[dst] + atomicAdd(&g_fill[dst], 1);
        g_col[pos] = src;
    } else {
        int idx = (blockIdx.x - nbScat) * blockDim.x + threadIdx.x;
        if (idx >= n * 32) return;       // n*32 half2 elements = n*64 halves
        int i = idx >> 5;
        float di = g_dinv[i];
        float2 v = h1[idx];
        hh[idx] = __floats2half2_rn(di * v.x, di * v.y);
    }
}

// ---------------- aggregation core (proven R7 path) ----------------
__device__ __forceinline__ void agg_sum16(const __half2* __restrict__ hh, int i, int lane,
                                          float& ax, float& ay) {
    int e = g_rowptr[i];
    const int end = g_rowptr[i + 1];
    for (; e + 3 < end; e += 4) {
        int s0 = __ldg(&g_col[e]);
        int s1 = __ldg(&g_col[e + 1]);
        int s2 = __ldg(&g_col[e + 2]);
        int s3 = __ldg(&g_col[e + 3]);
        float2 v0 = __half22float2(hh[(size_t)s0 * 32 + lane]);
        float2 v1 = __half22float2(hh[(size_t)s1 * 32 + lane]);
        float2 v2 = __half22float2(hh[(size_t)s2 * 32 + lane]);
        float2 v3 = __half22float2(hh[(size_t)s3 * 32 + lane]);
        ax += v0.x + v1.x + v2.x + v3.x;
        ay += v0.y + v1.y + v2.y + v3.y;
    }
    for (; e < end; e++) {
        int s0 = __ldg(&g_col[e]);
        float2 v0 = __half22float2(hh[(size_t)s0 * 32 + lane]);
        ax += v0.x;
        ay += v0.y;
    }
}

// layer 1: self term from RAW fp32 h1 (multiply dinv here); neighbors premultiplied fp16
__global__ __launch_bounds__(256) void agg_relu_kernel(const __half2* __restrict__ hh,
                                                       const float2* __restrict__ h1,
                                                       const float* __restrict__ bias,
                                                       float2* __restrict__ out, int n) {
    int wid = (blockIdx.x * blockDim.x + threadIdx.x) >> 5;
    int lane = threadIdx.x & 31;
    if (wid >= n) return;
    const int i = wid;
    float di = g_dinv[i];
    float2 self = h1[(size_t)i * 32 + lane];
    float ax = di * self.x, ay = di * self.y;
    agg_sum16(hh, i, lane, ax, ay);
    float2 bb = ((const float2*)bias)[lane];
    out[(size_t)i * 32 + lane] =
        make_float2(fmaxf(di * ax + bb.x, 0.f), fmaxf(di * ay + bb.y, 0.f));
}

// ---------------- kernel 5: gemm2 with dinv premult, fp32 + fp16 outputs ----------------
__global__ __launch_bounds__(256) void gemm2_dinv_kernel(const float* __restrict__ A,
                                                         const float* __restrict__ B,
                                                         float* __restrict__ C,
                                                         __half2* __restrict__ Ch, int M) {
    __shared__ float xs[128][32];
    __shared__ float ws[32][64];
    const int tid = threadIdx.x;
    const int tx = tid & 15, ty = tid >> 4;
    const int row0 = blockIdx.x * 128;
    const int K = 64;
    float acc[8][4] = {};

    for (int kt = 0; kt < K; kt += 32) {
        #pragma unroll
        for (int it = 0; it < 4; it++) {
            int idx = tid + it * 256;
            int r = idx >> 3, c4 = idx & 7;
            int grow = row0 + r;
            float4 v = make_float4(0.f, 0.f, 0.f, 0.f);
            if (grow < M) v = *(const float4*)&A[(size_t)grow * K + kt + c4 * 4];
            *(float4*)&xs[r][c4 * 4] = v;
        }
        #pragma unroll
        for (int it = 0; it < 2; it++) {
            int idx = tid + it * 256;
            int kk = idx >> 4, c4 = idx & 15;
            *(float4*)&ws[kk][c4 * 4] = *(const float4*)&B[(size_t)(kt + kk) * 64 + c4 * 4];
        }
        __syncthreads();
        #pragma unroll
        for (int k = 0; k < 32; k++) {
            float4 b = *(float4*)&ws[k][tx * 4];
            #pragma unroll
            for (int r = 0; r < 8; r++) {
                float a = xs[ty * 8 + r][k];
                acc[r][0] += a * b.x;
                acc[r][1] += a * b.y;
                acc[r][2] += a * b.z;
                acc[r][3] += a * b.w;
            }
        }
        __syncthreads();
    }
    #pragma unroll
    for (int r = 0; r < 8; r++) {
        int grow = row0 + ty * 8 + r;
        if (grow < M) {
            float di = g_dinv[grow];
            float4 o = make_float4(di * acc[r][0], di * acc[r][1], di * acc[r][2], di * acc[r][3]);
            *(float4*)&C[(size_t)grow * 64 + tx * 4] = o;
            Ch[(size_t)grow * 32 + tx * 2 + 0] = __floats2half2_rn(o.x, o.y);
            Ch[(size_t)grow * 32 + tx * 2 + 1] = __floats2half2_rn(o.z, o.w);
        }
    }
}

// ---------------- kernel 6: layer-2 aggregation fused with final FC; resets g_cnt ----------------
__global__ __launch_bounds__(256) void agg_fc_kernel(const __half2* __restrict__ hh,
                                                     const float2* __restrict__ hs,
                                                     const float* __restrict__ b2,
                                                     const float* __restrict__ Wfc,
                                                     const float* __restrict__ bfc,
                                                     float* __restrict__ out, int n) {
    __shared__ float Ws[64 * 11];
    __shared__ float bs[11];
    int tid = threadIdx.x;
    for (int q = tid; q < 64 * 11; q += 256) Ws[q] = Wfc[q];
    if (tid < 11) bs[tid] = bfc[tid];
    __syncthreads();

    int wid = (blockIdx.x * blockDim.x + tid) >> 5;
    int lane = tid & 31;
    if (wid >= n) return;
    const int i = wid;
    if (lane == 0) g_cnt[i] = 0;   // reset degree counter for next call
    float2 self = hs[(size_t)i * 32 + lane];   // premultiplied fp32 from gemm2
    float ax = self.x, ay = self.y;
    agg_sum16(hh, i, lane, ax, ay);
    float di = g_dinv[i];
    float2 bb = ((const float2*)b2)[lane];
    float vx = fmaxf(di * ax + bb.x, 0.f);
    float vy = fmaxf(di * ay + bb.y, 0.f);

    #pragma unroll
    for (int j = 0; j < 11; j++) {
        float p = vx * Ws[(2 * lane) * 11 + j] + vy * Ws[(2 * lane + 1) * 11 + j];
        #pragma unroll
        for (int o = 16; o; o >>= 1) p += __shfl_xor_sync(0xffffffffu, p, o);
        if (lane == j) out[(size_t)i * 11 + j] = p + bs[j];
    }
}

// ---------------- launch ----------------
extern "C" void kernel_launch(void* const* d_in, const int* in_sizes, int n_in,
                              void* d_out, int out_size) {
    const float* x   = (const float*)d_in[0];
    const void*  ei  = d_in[1];
    const float* W1  = (const float*)d_in[2];
    const float* b1  = (const float*)d_in[3];
    const float* W2  = (const float*)d_in[4];
    const float* b2  = (const float*)d_in[5];
    const float* Wfc = (const float*)d_in[6];
    const float* bfc = (const float*)d_in[7];
    float* out = (float*)d_out;

    const int n = in_sizes[0] / 256;   // 100000
    const int E = in_sizes[1] / 2;     // 1600000

    const int TB = 256;
    int nb_edge = (E + TB - 1) / TB;           // 6250
    int nb_gemm = (n + 127) / 128;             // 782
    int nb_conv = (n * 32 + TB - 1) / TB;      // 12500
    int nb_agg  = (n * 32 + TB - 1) / TB;      // 12500
    int nb_k1   = nb_edge > nb_gemm ? nb_edge : nb_gemm;

    // g_cnt zero at first call (BSS); reset by agg_fc each call.
    gemm1_count_kernel<<<nb_k1, TB>>>(x, W1, g_h1, n, ei, E);            // 1
    scan_kernel<<<1, 1024>>>(n);                                         // 2
    scatter_convert_kernel<<<nb_edge + nb_conv, TB>>>(ei, E, nb_edge,
                                  (const float2*)g_h1, g_hh, n);         // 3
    agg_relu_kernel<<<nb_agg, TB>>>(g_hh, (const float2*)g_h1, b1,
                                    (float2*)g_ha, n);                   // 4 <-- profiled (REAL data)
    gemm2_dinv_kernel<<<nb_gemm, TB>>>(g_ha, W2, g_h1, g_hh, n);         // 5
    agg_fc_kernel<<<nb_agg, TB>>>(g_hh, (const float2*)g_h1, b2,
                                  Wfc, bfc, out, n);                     // 6
}

// round 9
// speedup vs baseline: 1.1636x; 1.1636x over previous
#include <cuda_runtime.h>
#include <cuda_fp16.h>
#include <cstdint>

// Problem constants (fixed shapes per reference)
#define NN 100000
#define EE 1600000
#define HID 64

// ---------------- device scratch (no allocations allowed) ----------------
__device__ int   g_cnts[NN];       // out-degree (src) counter   [reset by agg_fc]
__device__ int   g_cntd[NN];       // in-degree (dst) counter    [reset by agg_fc]
__device__ int   g_fills[NN];      // ticket counters (zeroed by scan2 each call)
__device__ int   g_filld[NN];
__device__ int   g_rps[NN + 1];    // rowptr by src
__device__ int   g_rpd[NN + 1];    // rowptr by dst
__device__ float g_dinv[NN];
__device__ int2  g_e2[EE];         // edges sorted (approx) by src
__device__ int   g_col[EE];        // dst-CSR columns, ~ascending src per dst
__device__ __align__(16) float   g_h1[(size_t)NN * HID];    // premultiplied fp32 transform
__device__ __align__(16) __half2 g_hh[(size_t)NN * HID/2];  // fp16 premultiplied copy
__device__ __align__(16) float   g_ha[(size_t)NN * HID];    // post-aggregation activations

// per-warp edge dtype detection (int64 vs int32), no global state
__device__ __forceinline__ bool warp_is64(const void* ei) {
    int lane = threadIdx.x & 31;
    const long long* p = (const long long*)ei;
    long long v0 = p[lane * 2];
    long long v1 = p[lane * 2 + 1];
    bool ok = (v0 >= 0) && (v0 < NN) && (v1 >= 0) && (v1 < NN);
    return __all_sync(0xffffffffu, ok);
}

__device__ __forceinline__ void load_edge(const void* ei, int E, bool is64, int e,
                                          int& src, int& dst) {
    if (is64) {
        src = (int)((const long long*)ei)[e];
        dst = (int)((const long long*)ei)[E + e];
    } else {
        src = ((const int*)ei)[e];
        dst = ((const int*)ei)[E + e];
    }
}

// ---------------- 1: dual degree count ----------------
__global__ __launch_bounds__(256) void count2_kernel(const void* ei, int E) {
    bool is64 = warp_is64(ei);
    int e = blockIdx.x * blockDim.x + threadIdx.x;
    if (e >= E) return;
    int src, dst;
    load_edge(ei, E, is64, e, src, dst);
    atomicAdd(&g_cnts[src], 1);
    atomicAdd(&g_cntd[dst], 1);
}

// ---------------- 2: dual exclusive scan (src then dst); dinv; zero fills ----------------
__global__ __launch_bounds__(1024) void scan2_kernel(int n) {
    const int tid = threadIdx.x;
    __shared__ int wsum[32];
    __shared__ int carry;
    for (int phase = 0; phase < 2; phase++) {
        const int4* c4 = (const int4*)(phase ? g_cntd : g_cnts);
        int* rp   = phase ? g_rpd : g_rps;
        int* fill = phase ? g_filld : g_fills;
        if (tid == 0) carry = 0;
        __syncthreads();
        int nv4 = n >> 2;
        for (int base = 0; base < nv4; base += 1024) {
            int idx = base + tid;
            int4 v = make_int4(0, 0, 0, 0);
            if (idx < nv4) v = c4[idx];
            int s = v.x + v.y + v.z + v.w;
            int x = s;
            #pragma unroll
            for (int o = 1; o < 32; o <<= 1) {
                int y = __shfl_up_sync(0xffffffffu, x, o);
                if ((tid & 31) >= o) x += y;
            }
            if ((tid & 31) == 31) wsum[tid >> 5] = x;
            __syncthreads();
            if (tid < 32) {
                int w = wsum[tid];
                #pragma unroll
                for (int o = 1; o < 32; o <<= 1) {
                    int y = __shfl_up_sync(0xffffffffu, w, o);
                    if (tid >= o) w += y;
                }
                wsum[tid] = w;
            }
            __syncthreads();
            int excl = x - s + ((tid >= 32) ? wsum[(tid >> 5) - 1] : 0) + carry;
            if (idx < nv4) {
                rp[idx * 4 + 0] = excl;
                rp[idx * 4 + 1] = excl + v.x;
                rp[idx * 4 + 2] = excl + v.x + v.y;
                rp[idx * 4 + 3] = excl + v.x + v.y + v.z;
                *(int4*)&fill[idx * 4] = make_int4(0, 0, 0, 0);
                if (phase == 1)
                    *(float4*)&g_dinv[idx * 4] = make_float4(
                        rsqrtf((float)(v.x + 1)), rsqrtf((float)(v.y + 1)),
                        rsqrtf((float)(v.z + 1)), rsqrtf((float)(v.w + 1)));
            }
            __syncthreads();
            if (tid == 1023) carry = excl + s;
            __syncthreads();
        }
        if (tid == 0) rp[n] = carry;
        __syncthreads();
    }
}

// ---------------- 3: reorder edges by src (bucket scatter) ----------------
__global__ __launch_bounds__(256) void reorder_kernel(const void* ei, int E) {
    bool is64 = warp_is64(ei);
    int e = blockIdx.x * blockDim.x + threadIdx.x;
    if (e >= E) return;
    int src, dst;
    load_edge(ei, E, is64, e, src, dst);
    int pos = g_rps[src] + atomicAdd(&g_fills[src], 1);
    g_e2[pos] = make_int2(src, dst);
}

// ---------------- 4: fill dst-CSR walking the src-sorted edge list ----------------
// Processing order ~ascending p  =>  each dst's column list is ~ascending src.
__global__ __launch_bounds__(256) void scatter2_kernel(int E) {
    int p = blockIdx.x * blockDim.x + threadIdx.x;
    if (p >= E) return;
    int2 sd = g_e2[p];
    int pos = g_rpd[sd.y] + atomicAdd(&g_filld[sd.y], 1);
    g_col[pos] = sd.x;
}

// ---------------- GEMM: [M,K] @ [K,64] -> dinv[row]*result, fp32 + fp16 copies ----------------
template <int K>
__global__ __launch_bounds__(256) void gemm_dinv_kernel(const float* __restrict__ A,
                                                        const float* __restrict__ B,
                                                        float* __restrict__ C,
                                                        __half2* __restrict__ Ch, int M) {
    __shared__ float xs[128][32];  // [row][k]
    __shared__ float ws[32][64];   // [k][col]
    const int tid = threadIdx.x;
    const int tx = tid & 15, ty = tid >> 4;
    const int row0 = blockIdx.x * 128;

    float acc[8][4] = {};

    for (int kt = 0; kt < K; kt += 32) {
        #pragma unroll
        for (int it = 0; it < 4; it++) {
            int idx = tid + it * 256;
            int r = idx >> 3, c4 = idx & 7;
            int grow = row0 + r;
            float4 v = make_float4(0.f, 0.f, 0.f, 0.f);
            if (grow < M) v = *(const float4*)&A[(size_t)grow * K + kt + c4 * 4];
            *(float4*)&xs[r][c4 * 4] = v;
        }
        #pragma unroll
        for (int it = 0; it < 2; it++) {
            int idx = tid + it * 256;
            int kk = idx >> 4, c4 = idx & 15;
            *(float4*)&ws[kk][c4 * 4] = *(const float4*)&B[(size_t)(kt + kk) * 64 + c4 * 4];
        }
        __syncthreads();
        #pragma unroll
        for (int k = 0; k < 32; k++) {
            float4 b = *(float4*)&ws[k][tx * 4];
            #pragma unroll
            for (int r = 0; r < 8; r++) {
                float a = xs[ty * 8 + r][k];
                acc[r][0] += a * b.x;
                acc[r][1] += a * b.y;
                acc[r][2] += a * b.z;
                acc[r][3] += a * b.w;
            }
        }
        __syncthreads();
    }
    #pragma unroll
    for (int r = 0; r < 8; r++) {
        int grow = row0 + ty * 8 + r;
        if (grow < M) {
            float di = g_dinv[grow];
            float4 o = make_float4(di * acc[r][0], di * acc[r][1], di * acc[r][2], di * acc[r][3]);
            *(float4*)&C[(size_t)grow * 64 + tx * 4] = o;
            Ch[(size_t)grow * 32 + tx * 2 + 0] = __floats2half2_rn(o.x, o.y);
            Ch[(size_t)grow * 32 + tx * 2 + 1] = __floats2half2_rn(o.z, o.w);
        }
    }
}

// ---------------- aggregation core (proven R7 path; col lists now ~src-sorted) ----------------
__device__ __forceinline__ void agg_sum16(const __half2* __restrict__ hh, int i, int lane,
                                          float& ax, float& ay) {
    int e = g_rpd[i];
    const int end = g_rpd[i + 1];
    for (; e + 3 < end; e += 4) {
        int s0 = __ldg(&g_col[e]);
        int s1 = __ldg(&g_col[e + 1]);
        int s2 = __ldg(&g_col[e + 2]);
        int s3 = __ldg(&g_col[e + 3]);
        float2 v0 = __half22float2(hh[(size_t)s0 * 32 + lane]);
        float2 v1 = __half22float2(hh[(size_t)s1 * 32 + lane]);
        float2 v2 = __half22float2(hh[(size_t)s2 * 32 + lane]);
        float2 v3 = __half22float2(hh[(size_t)s3 * 32 + lane]);
        ax += v0.x + v1.x + v2.x + v3.x;
        ay += v0.y + v1.y + v2.y + v3.y;
    }
    for (; e < end; e++) {
        int s0 = __ldg(&g_col[e]);
        float2 v0 = __half22float2(hh[(size_t)s0 * 32 + lane]);
        ax += v0.x;
        ay += v0.y;
    }
}

// out[d] = relu(dinv[d]*(sum_nb hh[col] + hs[d]) + bias);  hs premultiplied fp32
__global__ __launch_bounds__(256) void agg_relu_kernel(const __half2* __restrict__ hh,
                                                       const float2* __restrict__ hs,
                                                       const float* __restrict__ bias,
                                                       float2* __restrict__ out, int n) {
    int wid = (blockIdx.x * blockDim.x + threadIdx.x) >> 5;
    int lane = threadIdx.x & 31;
    if (wid >= n) return;
    const int i = wid;
    float2 self = hs[(size_t)i * 32 + lane];
    float ax = self.x, ay = self.y;
    agg_sum16(hh, i, lane, ax, ay);
    float di = g_dinv[i];
    float2 bb = ((const float2*)bias)[lane];
    out[(size_t)i * 32 + lane] =
        make_float2(fmaxf(di * ax + bb.x, 0.f), fmaxf(di * ay + bb.y, 0.f));
}

// ---------------- layer-2 aggregation fused with final FC; resets count arrays ----------------
__global__ __launch_bounds__(256) void agg_fc_kernel(const __half2* __restrict__ hh,
                                                     const float2* __restrict__ hs,
                                                     const float* __restrict__ b2,
                                                     const float* __restrict__ Wfc,
                                                     const float* __restrict__ bfc,
                                                     float* __restrict__ out, int n) {
    __shared__ float Ws[64 * 11];
    __shared__ float bs[11];
    int tid = threadIdx.x;
    for (int q = tid; q < 64 * 11; q += 256) Ws[q] = Wfc[q];
    if (tid < 11) bs[tid] = bfc[tid];
    __syncthreads();

    int wid = (blockIdx.x * blockDim.x + tid) >> 5;
    int lane = tid & 31;
    if (wid >= n) return;
    const int i = wid;
    if (lane == 0) { g_cnts[i] = 0; g_cntd[i] = 0; }  // reset for next call
    float2 self = hs[(size_t)i * 32 + lane];
    float ax = self.x, ay = self.y;
    agg_sum16(hh, i, lane, ax, ay);
    float di = g_dinv[i];
    float2 bb = ((const float2*)b2)[lane];
    float vx = fmaxf(di * ax + bb.x, 0.f);
    float vy = fmaxf(di * ay + bb.y, 0.f);

    #pragma unroll
    for (int j = 0; j < 11; j++) {
        float p = vx * Ws[(2 * lane) * 11 + j] + vy * Ws[(2 * lane + 1) * 11 + j];
        #pragma unroll
        for (int o = 16; o; o >>= 1) p += __shfl_xor_sync(0xffffffffu, p, o);
        if (lane == j) out[(size_t)i * 11 + j] = p + bs[j];
    }
}

// ---------------- launch ----------------
extern "C" void kernel_launch(void* const* d_in, const int* in_sizes, int n_in,
                              void* d_out, int out_size) {
    const float* x   = (const float*)d_in[0];
    const void*  ei  = d_in[1];
    const float* W1  = (const float*)d_in[2];
    const float* b1  = (const float*)d_in[3];
    const float* W2  = (const float*)d_in[4];
    const float* b2  = (const float*)d_in[5];
    const float* Wfc = (const float*)d_in[6];
    const float* bfc = (const float*)d_in[7];
    float* out = (float*)d_out;

    const int n = in_sizes[0] / 256;   // 100000
    const int E = in_sizes[1] / 2;     // 1600000

    const int TB = 256;
    int nb_edge = (E + TB - 1) / TB;
    int nb_gemm = (n + 127) / 128;
    int nb_agg  = (n * 32 + TB - 1) / TB;

    // count arrays zero at first call (BSS); reset by agg_fc each call.
    count2_kernel<<<nb_edge, TB>>>(ei, E);                               // 1
    scan2_kernel<<<1, 1024>>>(n);                                        // 2
    reorder_kernel<<<nb_edge, TB>>>(ei, E);                              // 3
    scatter2_kernel<<<nb_edge, TB>>>(E);                                 // 4 <-- profiled
    gemm_dinv_kernel<256><<<nb_gemm, TB>>>(x, W1, g_h1, g_hh, n);        // 5
    agg_relu_kernel<<<nb_agg, TB>>>(g_hh, (const float2*)g_h1, b1,
                                    (float2*)g_ha, n);                   // 6
    gemm_dinv_kernel<64><<<nb_gemm, TB>>>(g_ha, W2, g_h1, g_hh, n);      // 7
    agg_fc_kernel<<<nb_agg, TB>>>(g_hh, (const float2*)g_h1, b2,
                                  Wfc, bfc, out, n);                     // 8
}

// round 11
// speedup vs baseline: 2.4142x; 2.0748x over previous
#include <cuda_runtime.h>
#include <cstdint>

// Problem constants (fixed shapes per reference)
#define NN 100000
#define EE 1600000
#define HID 64

// fixed-point scale for integer accumulation (2^22)
#define FPSCALE 4194304.0f
#define FPINV   (1.0f / 4194304.0f)

// ---------------- device scratch (no allocations allowed) ----------------
__device__ int   g_cnts[NN];       // out-degree (src) counter [reset by finish_fc]
__device__ int   g_cntd[NN];       // in-degree (dst) counter  [reset by finish_fc]
__device__ int   g_fills[NN];      // src ticket counters (zeroed by scan each call)
__device__ int   g_rps[NN + 1];    // rowptr by src
__device__ float g_dinv[NN];       // rsqrt(in-degree + 1)
__device__ int2  g_e2[EE];         // edges grouped by src
__device__ __align__(256) float g_h1[(size_t)NN * HID];   // premultiplied transform out
__device__ __align__(256) int   g_acci[(size_t)NN * HID]; // fixed-point push accumulator
__device__ __align__(256) float g_ha[(size_t)NN * HID];   // post-layer activations

// per-warp edge dtype detection (int64 vs int32), no global state
__device__ __forceinline__ bool warp_is64(const void* ei) {
    int lane = threadIdx.x & 31;
    const long long* p = (const long long*)ei;
    long long v0 = p[lane * 2];
    long long v1 = p[lane * 2 + 1];
    bool ok = (v0 >= 0) && (v0 < NN) && (v1 >= 0) && (v1 < NN);
    return __all_sync(0xffffffffu, ok);
}

__device__ __forceinline__ void load_edge(const void* ei, int E, bool is64, int e,
                                          int& src, int& dst) {
    if (is64) {
        src = (int)((const long long*)ei)[e];
        dst = (int)((const long long*)ei)[E + e];
    } else {
        src = ((const int*)ei)[e];
        dst = ((const int*)ei)[E + e];
    }
}

// ---------------- 1: dual degree count ----------------
__global__ __launch_bounds__(256) void count2_kernel(const void* ei, int E) {
    bool is64 = warp_is64(ei);
    int e = blockIdx.x * blockDim.x + threadIdx.x;
    if (e >= E) return;
    int src, dst;
    load_edge(ei, E, is64, e, src, dst);
    atomicAdd(&g_cnts[src], 1);
    atomicAdd(&g_cntd[dst], 1);
}

// ---------------- 2: scan src counts -> rowptr; dinv from dst counts; zero fills ----------------
__global__ __launch_bounds__(1024) void scan_kernel(int n) {
    const int tid = threadIdx.x;
    __shared__ int wsum[32];
    __shared__ int carry;
    if (tid == 0) carry = 0;
    __syncthreads();
    const int4* c4 = (const int4*)g_cnts;
    const int4* d4 = (const int4*)g_cntd;
    int nv4 = n >> 2;
    for (int base = 0; base < nv4; base += 1024) {
        int idx = base + tid;
        int4 v = make_int4(0, 0, 0, 0);
        if (idx < nv4) v = c4[idx];
        int s = v.x + v.y + v.z + v.w;
        int x = s;
        #pragma unroll
        for (int o = 1; o < 32; o <<= 1) {
            int y = __shfl_up_sync(0xffffffffu, x, o);
            if ((tid & 31) >= o) x += y;
        }
        if ((tid & 31) == 31) wsum[tid >> 5] = x;
        __syncthreads();
        if (tid < 32) {
            int w = wsum[tid];
            #pragma unroll
            for (int o = 1; o < 32; o <<= 1) {
                int y = __shfl_up_sync(0xffffffffu, w, o);
                if (tid >= o) w += y;
            }
            wsum[tid] = w;
        }
        __syncthreads();
        int excl = x - s + ((tid >= 32) ? wsum[(tid >> 5) - 1] : 0) + carry;
        if (idx < nv4) {
            g_rps[idx * 4 + 0] = excl;
            g_rps[idx * 4 + 1] = excl + v.x;
            g_rps[idx * 4 + 2] = excl + v.x + v.y;
            g_rps[idx * 4 + 3] = excl + v.x + v.y + v.z;
            *(int4*)&g_fills[idx * 4] = make_int4(0, 0, 0, 0);
            int4 d = d4[idx];
            *(float4*)&g_dinv[idx * 4] = make_float4(
                rsqrtf((float)(d.x + 1)), rsqrtf((float)(d.y + 1)),
                rsqrtf((float)(d.z + 1)), rsqrtf((float)(d.w + 1)));
        }
        __syncthreads();
        if (tid == 1023) carry = excl + s;
        __syncthreads();
    }
    if (tid == 0) g_rps[n] = carry;
}

// ---------------- 3: group edges by src (bucket scatter) ----------------
__global__ __launch_bounds__(256) void reorder_kernel(const void* ei, int E) {
    bool is64 = warp_is64(ei);
    int e = blockIdx.x * blockDim.x + threadIdx.x;
    if (e >= E) return;
    int src, dst;
    load_edge(ei, E, is64, e, src, dst);
    int pos = g_rps[src] + atomicAdd(&g_fills[src], 1);
    g_e2[pos] = make_int2(src, dst);
}

// ---------------- zero the fixed-point accumulator (plain stores) ----------------
__global__ __launch_bounds__(256) void zero_acc_kernel() {
    int i = blockIdx.x * blockDim.x + threadIdx.x;
    if (i < NN * HID / 4)
        *(int4*)&g_acci[(size_t)i * 4] = make_int4(0, 0, 0, 0);
}

// ---------------- GEMM: [M,K] @ [K,64] -> dinv[row] * result (fp32) ----------------
template <int K>
__global__ __launch_bounds__(256) void gemm_dinv_kernel(const float* __restrict__ A,
                                                        const float* __restrict__ B,
                                                        float* __restrict__ C, int M) {
    __shared__ float xs[128][32];  // [row][k]
    __shared__ float ws[32][64];   // [k][col]
    const int tid = threadIdx.x;
    const int tx = tid & 15, ty = tid >> 4;
    const int row0 = blockIdx.x * 128;

    float acc[8][4] = {};

    for (int kt = 0; kt < K; kt += 32) {
        #pragma unroll
        for (int it = 0; it < 4; it++) {
            int idx = tid + it * 256;
            int r = idx >> 3, c4 = idx & 7;
            int grow = row0 + r;
            float4 v = make_float4(0.f, 0.f, 0.f, 0.f);
            if (grow < M) v = *(const float4*)&A[(size_t)grow * K + kt + c4 * 4];
            *(float4*)&xs[r][c4 * 4] = v;
        }
        #pragma unroll
        for (int it = 0; it < 2; it++) {
            int idx = tid + it * 256;
            int kk = idx >> 4, c4 = idx & 15;
            *(float4*)&ws[kk][c4 * 4] = *(const float4*)&B[(size_t)(kt + kk) * 64 + c4 * 4];
        }
        __syncthreads();
        #pragma unroll
        for (int k = 0; k < 32; k++) {
            float4 b = *(float4*)&ws[k][tx * 4];
            #pragma unroll
            for (int r = 0; r < 8; r++) {
                float a = xs[ty * 8 + r][k];
                acc[r][0] += a * b.x;
                acc[r][1] += a * b.y;
                acc[r][2] += a * b.z;
                acc[r][3] += a * b.w;
            }
        }
        __syncthreads();
    }
    #pragma unroll
    for (int r = 0; r < 8; r++) {
        int grow = row0 + ty * 8 + r;
        if (grow < M) {
            float di = g_dinv[grow];
            *(float4*)&C[(size_t)grow * 64 + tx * 4] =
                make_float4(di * acc[r][0], di * acc[r][1], di * acc[r][2], di * acc[r][3]);
        }
    }
}

// ---------------- push: acci[dst] += fix(hp[src])  (warp per edge) ----------------
// Edges grouped by src => consecutive warps read the SAME hp row (L1 broadcast).
// Random side: fire-and-forget int REDG (proven primitive), fixed-point 2^22.
__global__ __launch_bounds__(256) void push_kernel(int E, const float2* __restrict__ hp) {
    int w = (blockIdx.x * blockDim.x + threadIdx.x) >> 5;
    int lane = threadIdx.x & 31;
    if (w >= E) return;
    int2 sd = g_e2[w];
    float2 v = hp[(size_t)sd.x * 32 + lane];
    int* p = &g_acci[(size_t)sd.y * 64 + lane * 2];
    atomicAdd(p + 0, __float2int_rn(v.x * FPSCALE));
    atomicAdd(p + 1, __float2int_rn(v.y * FPSCALE));
}

// ---------------- finish layer 1: ha = relu(dinv*(acc + self) + b) ----------------
__global__ __launch_bounds__(256) void finish_relu_kernel(const float2* __restrict__ hp,
                                                          const float* __restrict__ bias,
                                                          float2* __restrict__ out, int n) {
    int gid = blockIdx.x * blockDim.x + threadIdx.x;
    if (gid >= n * 32) return;
    int i = gid >> 5;
    int l = gid & 31;
    float di = g_dinv[i];
    int2 a = *(const int2*)&g_acci[(size_t)gid * 2];
    float2 s = hp[gid];
    float2 bb = ((const float2*)bias)[l];
    out[gid] = make_float2(fmaxf(di * ((float)a.x * FPINV + s.x) + bb.x, 0.f),
                           fmaxf(di * ((float)a.y * FPINV + s.y) + bb.y, 0.f));
}

// ---------------- finish layer 2 fused with final FC; resets counters ----------------
__global__ __launch_bounds__(256) void finish_fc_kernel(const float2* __restrict__ hp,
                                                        const float* __restrict__ b2,
                                                        const float* __restrict__ Wfc,
                                                        const float* __restrict__ bfc,
                                                        float* __restrict__ out, int n) {
    __shared__ float Ws[64 * 11];
    __shared__ float bs[11];
    int tid = threadIdx.x;
    for (int q = tid; q < 64 * 11; q += 256) Ws[q] = Wfc[q];
    if (tid < 11) bs[tid] = bfc[tid];
    __syncthreads();

    int wid = (blockIdx.x * blockDim.x + tid) >> 5;
    int lane = tid & 31;
    if (wid >= n) return;
    const int i = wid;
    if (lane == 0) { g_cnts[i] = 0; g_cntd[i] = 0; }  // reset for next call
    float di = g_dinv[i];
    int2 a = *(const int2*)&g_acci[(size_t)i * 64 + lane * 2];
    float2 s = hp[(size_t)i * 32 + lane];
    float2 bb = ((const float2*)b2)[lane];
    float vx = fmaxf(di * ((float)a.x * FPINV + s.x) + bb.x, 0.f);
    float vy = fmaxf(di * ((float)a.y * FPINV + s.y) + bb.y, 0.f);

    // fused FC: lane holds features 2*lane, 2*lane+1
    #pragma unroll
    for (int j = 0; j < 11; j++) {
        float p = vx * Ws[(2 * lane) * 11 + j] + vy * Ws[(2 * lane + 1) * 11 + j];
        #pragma unroll
        for (int o = 16; o; o >>= 1) p += __shfl_xor_sync(0xffffffffu, p, o);
        if (lane == j) out[(size_t)i * 11 + j] = p + bs[j];
    }
}

// ---------------- launch ----------------
extern "C" void kernel_launch(void* const* d_in, const int* in_sizes, int n_in,
                              void* d_out, int out_size) {
    const float* x   = (const float*)d_in[0];
    const void*  ei  = d_in[1];
    const float* W1  = (const float*)d_in[2];
    const float* b1  = (const float*)d_in[3];
    const float* W2  = (const float*)d_in[4];
    const float* b2  = (const float*)d_in[5];
    const float* Wfc = (const float*)d_in[6];
    const float* bfc = (const float*)d_in[7];
    float* out = (float*)d_out;

    const int n = in_sizes[0] / 256;   // 100000
    const int E = in_sizes[1] / 2;     // 1600000

    const int TB = 256;
    int nb_edge = (E + TB - 1) / TB;                         // 6250
    int nb_gemm = (n + 127) / 128;                           // 782
    int nb_push = (int)(((long long)E * 32 + TB - 1) / TB);  // 200000
    int nb_fin  = (n * 32 + TB - 1) / TB;                    // 12500
    int nb_zero = (NN * HID / 4 + TB - 1) / TB;              // 6250

    // counters zero at first call (BSS); reset by finish_fc each call.
    count2_kernel<<<nb_edge, TB>>>(ei, E);                                  // 1
    scan_kernel<<<1, 1024>>>(n);                                            // 2
    reorder_kernel<<<nb_edge, TB>>>(ei, E);                                 // 3
    gemm_dinv_kernel<256><<<nb_gemm, TB>>>(x, W1, g_h1, n);                 // 4 <-- profiled
    zero_acc_kernel<<<nb_zero, TB>>>();                                     // 5
    push_kernel<<<nb_push, TB>>>(E, (const float2*)g_h1);                   // 6
    finish_relu_kernel<<<nb_fin, TB>>>((const float2*)g_h1, b1,
                                       (float2*)g_ha, n);                   // 7
    gemm_dinv_kernel<64><<<nb_gemm, TB>>>(g_ha, W2, g_h1, n);               // 8
    zero_acc_kernel<<<nb_zero, TB>>>();                                     // 9
    push_kernel<<<nb_push, TB>>>(E, (const float2*)g_h1);                   // 10
    finish_fc_kernel<<<nb_fin, TB>>>((const float2*)g_h1, b2,
                                     Wfc, bfc, out, n);                     // 11
}

// round 13
// speedup vs baseline: 2.4197x; 1.0023x over previous
#include <cuda_runtime.h>
#include <cstdint>

// Problem constants (fixed shapes per reference)
#define NN 100000
#define EE 1600000
#define HID 64

// fixed-point scale 2^20; per-term bias 2^24 keeps both packed halves positive
#define FPSCALE 1048576.0f
#define FPINV   (1.0f / 1048576.0f)
#define FPBIAS  (1 << 24)

// ---------------- device scratch (no allocations allowed) ----------------
__device__ int   g_cnts[NN];       // out-degree (src) counter [reset by finish_fc]
__device__ int   g_cntd[NN];       // in-degree (dst) counter  [reset by finish_fc]
__device__ int   g_fills[NN];      // src ticket counters (zeroed by scan each call)
__device__ int   g_rps[NN + 1];    // rowptr by src
__device__ float g_dinv[NN];       // rsqrt(in-degree + 1)
__device__ int2  g_e2[EE];         // edges grouped by src
__device__ __align__(256) float g_h1[(size_t)NN * HID];  // premultiplied transform out
__device__ __align__(256) unsigned long long g_accu[(size_t)NN * 32]; // packed accumulator
__device__ __align__(256) float g_ha[(size_t)NN * HID];  // post-layer activations

// per-warp edge dtype detection (int64 vs int32), no global state
__device__ __forceinline__ bool warp_is64(const void* ei) {
    int lane = threadIdx.x & 31;
    const long long* p = (const long long*)ei;
    long long v0 = p[lane * 2];
    long long v1 = p[lane * 2 + 1];
    bool ok = (v0 >= 0) && (v0 < NN) && (v1 >= 0) && (v1 < NN);
    return __all_sync(0xffffffffu, ok);
}

__device__ __forceinline__ void load_edge(const void* ei, int E, bool is64, int e,
                                          int& src, int& dst) {
    if (is64) {
        src = (int)((const long long*)ei)[e];
        dst = (int)((const long long*)ei)[E + e];
    } else {
        src = ((const int*)ei)[e];
        dst = ((const int*)ei)[E + e];
    }
}

// ---------------- 1: dual degree count ----------------
__global__ __launch_bounds__(256) void count2_kernel(const void* ei, int E) {
    bool is64 = warp_is64(ei);
    int e = blockIdx.x * blockDim.x + threadIdx.x;
    if (e >= E) return;
    int src, dst;
    load_edge(ei, E, is64, e, src, dst);
    atomicAdd(&g_cnts[src], 1);
    atomicAdd(&g_cntd[dst], 1);
}

// ---------------- 2: scan src counts -> rowptr; dinv from dst counts; zero fills ----------------
__global__ __launch_bounds__(1024) void scan_kernel(int n) {
    const int tid = threadIdx.x;
    __shared__ int wsum[32];
    __shared__ int carry;
    if (tid == 0) carry = 0;
    __syncthreads();
    const int4* c4 = (const int4*)g_cnts;
    const int4* d4 = (const int4*)g_cntd;
    int nv4 = n >> 2;
    for (int base = 0; base < nv4; base += 1024) {
        int idx = base + tid;
        int4 v = make_int4(0, 0, 0, 0);
        if (idx < nv4) v = c4[idx];
        int s = v.x + v.y + v.z + v.w;
        int x = s;
        #pragma unroll
        for (int o = 1; o < 32; o <<= 1) {
            int y = __shfl_up_sync(0xffffffffu, x, o);
            if ((tid & 31) >= o) x += y;
        }
        if ((tid & 31) == 31) wsum[tid >> 5] = x;
        __syncthreads();
        if (tid < 32) {
            int w = wsum[tid];
            #pragma unroll
            for (int o = 1; o < 32; o <<= 1) {
                int y = __shfl_up_sync(0xffffffffu, w, o);
                if (tid >= o) w += y;
            }
            wsum[tid] = w;
        }
        __syncthreads();
        int excl = x - s + ((tid >= 32) ? wsum[(tid >> 5) - 1] : 0) + carry;
        if (idx < nv4) {
            g_rps[idx * 4 + 0] = excl;
            g_rps[idx * 4 + 1] = excl + v.x;
            g_rps[idx * 4 + 2] = excl + v.x + v.y;
            g_rps[idx * 4 + 3] = excl + v.x + v.y + v.z;
            *(int4*)&g_fills[idx * 4] = make_int4(0, 0, 0, 0);
            int4 d = d4[idx];
            *(float4*)&g_dinv[idx * 4] = make_float4(
                rsqrtf((float)(d.x + 1)), rsqrtf((float)(d.y + 1)),
                rsqrtf((float)(d.z + 1)), rsqrtf((float)(d.w + 1)));
        }
        __syncthreads();
        if (tid == 1023) carry = excl + s;
        __syncthreads();
    }
    if (tid == 0) g_rps[n] = carry;
}

// ---------------- 3: group edges by src (bucket scatter) ----------------
__global__ __launch_bounds__(256) void reorder_kernel(const void* ei, int E) {
    bool is64 = warp_is64(ei);
    int e = blockIdx.x * blockDim.x + threadIdx.x;
    if (e >= E) return;
    int src, dst;
    load_edge(ei, E, is64, e, src, dst);
    int pos = g_rps[src] + atomicAdd(&g_fills[src], 1);
    g_e2[pos] = make_int2(src, dst);
}

// ---------------- zero the packed accumulator (plain stores) ----------------
__global__ __launch_bounds__(256) void zero_acc_kernel() {
    int i = blockIdx.x * blockDim.x + threadIdx.x;
    if (i < NN * 16)
        *(ulonglong2*)&g_accu[(size_t)i * 2] = make_ulonglong2(0ull, 0ull);
}

// ---------------- GEMM: [M,K] @ [K,64] -> dinv[row] * result (fp32) ----------------
// xs row stride 32 floats (128B): float4 ops stay 16B-aligned. Within a warp
// only 2 distinct xs rows are read per k (ty in {0,1} per warp) -> <=2-way LDS.
template <int K>
__global__ __launch_bounds__(256) void gemm_dinv_kernel(const float* __restrict__ A,
                                                        const float* __restrict__ B,
                                                        float* __restrict__ C, int M) {
    __shared__ float xs[128][32];  // [row][k]
    __shared__ float ws[32][64];   // [k][col]
    const int tid = threadIdx.x;
    const int tx = tid & 15, ty = tid >> 4;
    const int row0 = blockIdx.x * 128;

    float acc[8][4] = {};

    for (int kt = 0; kt < K; kt += 32) {
        #pragma unroll
        for (int it = 0; it < 4; it++) {
            int idx = tid + it * 256;
            int r = idx >> 3, c4 = idx & 7;
            int grow = row0 + r;
            float4 v = make_float4(0.f, 0.f, 0.f, 0.f);
            if (grow < M) v = *(const float4*)&A[(size_t)grow * K + kt + c4 * 4];
            *(float4*)&xs[r][c4 * 4] = v;
        }
        #pragma unroll
        for (int it = 0; it < 2; it++) {
            int idx = tid + it * 256;
            int kk = idx >> 4, c4 = idx & 15;
            *(float4*)&ws[kk][c4 * 4] = *(const float4*)&B[(size_t)(kt + kk) * 64 + c4 * 4];
        }
        __syncthreads();
        #pragma unroll
        for (int k = 0; k < 32; k++) {
            float4 b = *(float4*)&ws[k][tx * 4];
            #pragma unroll
            for (int r = 0; r < 8; r++) {
                float a = xs[ty * 8 + r][k];
                acc[r][0] += a * b.x;
                acc[r][1] += a * b.y;
                acc[r][2] += a * b.z;
                acc[r][3] += a * b.w;
            }
        }
        __syncthreads();
    }
    #pragma unroll
    for (int r = 0; r < 8; r++) {
        int grow = row0 + ty * 8 + r;
        if (grow < M) {
            float di = g_dinv[grow];
            *(float4*)&C[(size_t)grow * 64 + tx * 4] =
                make_float4(di * acc[r][0], di * acc[r][1], di * acc[r][2], di * acc[r][3]);
        }
    }
}

// ---------------- push: accu[dst] += pack(hp[src])  (warp per edge) ----------------
// Edges grouped by src => consecutive warps read the SAME hp row (L1 broadcast).
// One 64-bit REDG per lane: two fixed-point values, each biased by 2^24 so both
// halves stay positive (no carry across bit 32). Worst case deg~45, |v|<5:
// half-sum < 45*(5*2^20 + 2^24) ~ 1.0e9 < 2^31.
__global__ __launch_bounds__(256) void push_kernel(int E, const float2* __restrict__ hp) {
    int w = (blockIdx.x * blockDim.x + threadIdx.x) >> 5;
    int lane = threadIdx.x & 31;
    if (w >= E) return;
    int2 sd = g_e2[w];
    float2 v = hp[(size_t)sd.x * 32 + lane];
    unsigned int lo = (unsigned int)(__float2int_rn(v.x * FPSCALE) + FPBIAS);
    unsigned int hi = (unsigned int)(__float2int_rn(v.y * FPSCALE) + FPBIAS);
    unsigned long long pack = ((unsigned long long)hi << 32) | (unsigned long long)lo;
    atomicAdd(&g_accu[(size_t)sd.y * 32 + lane], pack);
}

// unpack helper: integer bias subtraction (float would lose low bits at ~1e9)
__device__ __forceinline__ float2 unpack_acc(unsigned long long a, int deg) {
    int corr = deg * FPBIAS;
    int lo = (int)(unsigned int)(a & 0xffffffffull) - corr;
    int hi = (int)(unsigned int)(a >> 32) - corr;
    return make_float2((float)lo * FPINV, (float)hi * FPINV);
}

// ---------------- finish layer 1: ha = relu(dinv*(acc + self) + b) ----------------
__global__ __launch_bounds__(256) void finish_relu_kernel(const float2* __restrict__ hp,
                                                          const float* __restrict__ bias,
                                                          float2* __restrict__ out, int n) {
    int gid = blockIdx.x * blockDim.x + threadIdx.x;
    if (gid >= n * 32) return;
    int i = gid >> 5;
    int l = gid & 31;
    float di = g_dinv[i];
    float2 a = unpack_acc(g_accu[gid], g_cntd[i]);
    float2 s = hp[gid];
    float2 bb = ((const float2*)bias)[l];
    out[gid] = make_float2(fmaxf(di * (a.x + s.x) + bb.x, 0.f),
                           fmaxf(di * (a.y + s.y) + bb.y, 0.f));
}

// ---------------- finish layer 2 fused with final FC; resets counters ----------------
__global__ __launch_bounds__(256) void finish_fc_kernel(const float2* __restrict__ hp,
                                                        const float* __restrict__ b2,
                                                        const float* __restrict__ Wfc,
                                                        const float* __restrict__ bfc,
                                                        float* __restrict__ out, int n) {
    __shared__ float Ws[64 * 11];
    __shared__ float bs[11];
    int tid = threadIdx.x;
    for (int q = tid; q < 64 * 11; q += 256) Ws[q] = Wfc[q];
    if (tid < 11) bs[tid] = bfc[tid];
    __syncthreads();

    int wid = (blockIdx.x * blockDim.x + tid) >> 5;
    int lane = tid & 31;
    if (wid >= n) return;
    const int i = wid;
    int deg = g_cntd[i];
    if (lane == 0) { g_cnts[i] = 0; g_cntd[i] = 0; }  // reset for next call
    float di = g_dinv[i];
    float2 a = unpack_acc(g_accu[(size_t)i * 32 + lane], deg);
    float2 s = hp[(size_t)i * 32 + lane];
    float2 bb = ((const float2*)b2)[lane];
    float vx = fmaxf(di * (a.x + s.x) + bb.x, 0.f);
    float vy = fmaxf(di * (a.y + s.y) + bb.y, 0.f);

    // fused FC: lane holds features 2*lane, 2*lane+1
    #pragma unroll
    for (int j = 0; j < 11; j++) {
        float p = vx * Ws[(2 * lane) * 11 + j] + vy * Ws[(2 * lane + 1) * 11 + j];
        #pragma unroll
        for (int o = 16; o; o >>= 1) p += __shfl_xor_sync(0xffffffffu, p, o);
        if (lane == j) out[(size_t)i * 11 + j] = p + bs[j];
    }
}

// ---------------- launch ----------------
extern "C" void kernel_launch(void* const* d_in, const int* in_sizes, int n_in,
                              void* d_out, int out_size) {
    const float* x   = (const float*)d_in[0];
    const void*  ei  = d_in[1];
    const float* W1  = (const float*)d_in[2];
    const float* b1  = (const float*)d_in[3];
    const float* W2  = (const float*)d_in[4];
    const float* b2  = (const float*)d_in[5];
    const float* Wfc = (const float*)d_in[6];
    const float* bfc = (const float*)d_in[7];
    float* out = (float*)d_out;

    const int n = in_sizes[0] / 256;   // 100000
    const int E = in_sizes[1] / 2;     // 1600000

    const int TB = 256;
    int nb_edge = (E + TB - 1) / TB;                         // 6250
    int nb_gemm = (n + 127) / 128;                           // 782
    int nb_push = (int)(((long long)E * 32 + TB - 1) / TB);  // 200000
    int nb_fin  = (n * 32 + TB - 1) / TB;                    // 12500
    int nb_zero = (NN * 16 + TB - 1) / TB;                   // 6250

    // counters zero at first call (BSS); reset by finish_fc each call.
    count2_kernel<<<nb_edge, TB>>>(ei, E);                                  // 1
    scan_kernel<<<1, 1024>>>(n);                                            // 2
    reorder_kernel<<<nb_edge, TB>>>(ei, E);                                 // 3
    gemm_dinv_kernel<256><<<nb_gemm, TB>>>(x, W1, g_h1, n);                 // 4 <-- profiled
    zero_acc_kernel<<<nb_zero, TB>>>();                                     // 5
    push_kernel<<<nb_push, TB>>>(E, (const float2*)g_h1);                   // 6
    finish_relu_kernel<<<nb_fin, TB>>>((const float2*)g_h1, b1,
                                       (float2*)g_ha, n);                   // 7
    gemm_dinv_kernel<64><<<nb_gemm, TB>>>(g_ha, W2, g_h1, n);               // 8
    zero_acc_kernel<<<nb_zero, TB>>>();                                     // 9
    push_kernel<<<nb_push, TB>>>(E, (const float2*)g_h1);                   // 10
    finish_fc_kernel<<<nb_fin, TB>>>((const float2*)g_h1, b2,
                                     Wfc, bfc, out, n);                     // 11
}

// round 14
// speedup vs baseline: 3.5192x; 1.4544x over previous
#include <cuda_runtime.h>
#include <cstdint>

// Problem constants (fixed shapes per reference)
#define NN 100000
#define EE 1600000
#define HID 64

// fixed-point scale 2^20; per-term bias 2^24 keeps both packed halves positive
#define FPSCALE 1048576.0f
#define FPINV   (1.0f / 1048576.0f)
#define FPBIAS  (1 << 24)

// ---------------- device scratch (no allocations allowed) ----------------
__device__ int   g_cnts[NN];       // out-degree (src) counter [reset by finish_fc]
__device__ int   g_cntd[NN];       // in-degree (dst) counter  [reset by finish_fc]
__device__ int   g_fills[NN];      // src ticket counters (zeroed by scan each call)
__device__ int   g_rps[NN + 1];    // rowptr by src
__device__ float g_dinv[NN];       // rsqrt(in-degree + 1)
__device__ int   g_dstl[EE];       // dst list grouped by src
__device__ __align__(256) float g_h1[(size_t)NN * HID];  // premultiplied transform out
__device__ __align__(256) unsigned long long g_accu[(size_t)NN * 32]; // packed accumulator
__device__ __align__(256) float g_ha[(size_t)NN * HID];  // post-layer activations

// per-warp edge dtype detection (int64 vs int32), no global state
__device__ __forceinline__ bool warp_is64(const void* ei) {
    int lane = threadIdx.x & 31;
    const long long* p = (const long long*)ei;
    long long v0 = p[lane * 2];
    long long v1 = p[lane * 2 + 1];
    bool ok = (v0 >= 0) && (v0 < NN) && (v1 >= 0) && (v1 < NN);
    return __all_sync(0xffffffffu, ok);
}

__device__ __forceinline__ void load_edge(const void* ei, int E, bool is64, int e,
                                          int& src, int& dst) {
    if (is64) {
        src = (int)((const long long*)ei)[e];
        dst = (int)((const long long*)ei)[E + e];
    } else {
        src = ((const int*)ei)[e];
        dst = ((const int*)ei)[E + e];
    }
}

// ---------------- 1: dual degree count ----------------
__global__ __launch_bounds__(256) void count2_kernel(const void* ei, int E) {
    bool is64 = warp_is64(ei);
    int e = blockIdx.x * blockDim.x + threadIdx.x;
    if (e >= E) return;
    int src, dst;
    load_edge(ei, E, is64, e, src, dst);
    atomicAdd(&g_cnts[src], 1);
    atomicAdd(&g_cntd[dst], 1);
}

// ---------------- 2: scan src counts -> rowptr; dinv from dst counts; zero fills ----------------
__global__ __launch_bounds__(1024) void scan_kernel(int n) {
    const int tid = threadIdx.x;
    __shared__ int wsum[32];
    __shared__ int carry;
    if (tid == 0) carry = 0;
    __syncthreads();
    const int4* c4 = (const int4*)g_cnts;
    const int4* d4 = (const int4*)g_cntd;
    int nv4 = n >> 2;
    for (int base = 0; base < nv4; base += 1024) {
        int idx = base + tid;
        int4 v = make_int4(0, 0, 0, 0);
        if (idx < nv4) v = c4[idx];
        int s = v.x + v.y + v.z + v.w;
        int x = s;
        #pragma unroll
        for (int o = 1; o < 32; o <<= 1) {
            int y = __shfl_up_sync(0xffffffffu, x, o);
            if ((tid & 31) >= o) x += y;
        }
        if ((tid & 31) == 31) wsum[tid >> 5] = x;
        __syncthreads();
        if (tid < 32) {
            int w = wsum[tid];
            #pragma unroll
            for (int o = 1; o < 32; o <<= 1) {
                int y = __shfl_up_sync(0xffffffffu, w, o);
                if (tid >= o) w += y;
            }
            wsum[tid] = w;
        }
        __syncthreads();
        int excl = x - s + ((tid >= 32) ? wsum[(tid >> 5) - 1] : 0) + carry;
        if (idx < nv4) {
            g_rps[idx * 4 + 0] = excl;
            g_rps[idx * 4 + 1] = excl + v.x;
            g_rps[idx * 4 + 2] = excl + v.x + v.y;
            g_rps[idx * 4 + 3] = excl + v.x + v.y + v.z;
            *(int4*)&g_fills[idx * 4] = make_int4(0, 0, 0, 0);
            int4 d = d4[idx];
            *(float4*)&g_dinv[idx * 4] = make_float4(
                rsqrtf((float)(d.x + 1)), rsqrtf((float)(d.y + 1)),
                rsqrtf((float)(d.z + 1)), rsqrtf((float)(d.w + 1)));
        }
        __syncthreads();
        if (tid == 1023) carry = excl + s;
        __syncthreads();
    }
    if (tid == 0) g_rps[n] = carry;
}

// ---------------- 3: group dsts by src (bucket scatter) ----------------
__global__ __launch_bounds__(256) void reorder_kernel(const void* ei, int E) {
    bool is64 = warp_is64(ei);
    int e = blockIdx.x * blockDim.x + threadIdx.x;
    if (e >= E) return;
    int src, dst;
    load_edge(ei, E, is64, e, src, dst);
    int pos = g_rps[src] + atomicAdd(&g_fills[src], 1);
    g_dstl[pos] = dst;
}

// ---------------- zero the packed accumulator (plain stores) ----------------
__global__ __launch_bounds__(256) void zero_acc_kernel() {
    int i = blockIdx.x * blockDim.x + threadIdx.x;
    if (i < NN * 16)
        *(ulonglong2*)&g_accu[(size_t)i * 2] = make_ulonglong2(0ull, 0ull);
}

// ---------------- GEMM: [M,K] @ [K,64] -> dinv[row] * result (fp32) ----------------
template <int K>
__global__ __launch_bounds__(256) void gemm_dinv_kernel(const float* __restrict__ A,
                                                        const float* __restrict__ B,
                                                        float* __restrict__ C, int M) {
    __shared__ float xs[128][32];  // [row][k]
    __shared__ float ws[32][64];   // [k][col]
    const int tid = threadIdx.x;
    const int tx = tid & 15, ty = tid >> 4;
    const int row0 = blockIdx.x * 128;

    float acc[8][4] = {};

    for (int kt = 0; kt < K; kt += 32) {
        #pragma unroll
        for (int it = 0; it < 4; it++) {
            int idx = tid + it * 256;
            int r = idx >> 3, c4 = idx & 7;
            int grow = row0 + r;
            float4 v = make_float4(0.f, 0.f, 0.f, 0.f);
            if (grow < M) v = *(const float4*)&A[(size_t)grow * K + kt + c4 * 4];
            *(float4*)&xs[r][c4 * 4] = v;
        }
        #pragma unroll
        for (int it = 0; it < 2; it++) {
            int idx = tid + it * 256;
            int kk = idx >> 4, c4 = idx & 15;
            *(float4*)&ws[kk][c4 * 4] = *(const float4*)&B[(size_t)(kt + kk) * 64 + c4 * 4];
        }
        __syncthreads();
        #pragma unroll
        for (int k = 0; k < 32; k++) {
            float4 b = *(float4*)&ws[k][tx * 4];
            #pragma unroll
            for (int r = 0; r < 8; r++) {
                float a = xs[ty * 8 + r][k];
                acc[r][0] += a * b.x;
                acc[r][1] += a * b.y;
                acc[r][2] += a * b.z;
                acc[r][3] += a * b.w;
            }
        }
        __syncthreads();
    }
    #pragma unroll
    for (int r = 0; r < 8; r++) {
        int grow = row0 + ty * 8 + r;
        if (grow < M) {
            float di = g_dinv[grow];
            *(float4*)&C[(size_t)grow * 64 + tx * 4] =
                make_float4(di * acc[r][0], di * acc[r][1], di * acc[r][2], di * acc[r][3]);
        }
    }
}

// ---------------- push: warp per SRC node ----------------
// Row loaded + packed ONCE per src; per out-edge only shfl(dst) + RED.64.
// One 64-bit REDG per lane: two fixed-point values, each biased by 2^24 so both
// halves stay positive. Worst case deg~45, |v|<5: half-sum < 1.0e9 < 2^31.
__global__ __launch_bounds__(256) void push_kernel(int n, const float2* __restrict__ hp) {
    int i = (blockIdx.x * blockDim.x + threadIdx.x) >> 5;  // src node
    int lane = threadIdx.x & 31;
    if (i >= n) return;
    int e0 = g_rps[i];
    const int e1 = g_rps[i + 1];
    if (e0 == e1) return;
    float2 v = hp[(size_t)i * 32 + lane];
    unsigned int lo = (unsigned int)(__float2int_rn(v.x * FPSCALE) + FPBIAS);
    unsigned int hi = (unsigned int)(__float2int_rn(v.y * FPSCALE) + FPBIAS);
    unsigned long long pack = ((unsigned long long)hi << 32) | (unsigned long long)lo;

    for (int base = e0; base < e1; base += 32) {
        int idx = base + lane;
        int d = (idx < e1) ? g_dstl[idx] : 0;
        const int m = min(32, e1 - base);
        int j = 0;
        for (; j + 4 <= m; j += 4) {
            int d0 = __shfl_sync(0xffffffffu, d, j + 0);
            int d1 = __shfl_sync(0xffffffffu, d, j + 1);
            int d2 = __shfl_sync(0xffffffffu, d, j + 2);
            int d3 = __shfl_sync(0xffffffffu, d, j + 3);
            atomicAdd(&g_accu[(size_t)d0 * 32 + lane], pack);
            atomicAdd(&g_accu[(size_t)d1 * 32 + lane], pack);
            atomicAdd(&g_accu[(size_t)d2 * 32 + lane], pack);
            atomicAdd(&g_accu[(size_t)d3 * 32 + lane], pack);
        }
        for (; j < m; j++) {
            int dj = __shfl_sync(0xffffffffu, d, j);
            atomicAdd(&g_accu[(size_t)dj * 32 + lane], pack);
        }
    }
}

// unpack helper: integer bias subtraction (float would lose low bits at ~1e9)
__device__ __forceinline__ float2 unpack_acc(unsigned long long a, int deg) {
    int corr = deg * FPBIAS;
    int lo = (int)(unsigned int)(a & 0xffffffffull) - corr;
    int hi = (int)(unsigned int)(a >> 32) - corr;
    return make_float2((float)lo * FPINV, (float)hi * FPINV);
}

// ---------------- finish layer 1: ha = relu(dinv*(acc + self) + b) ----------------
__global__ __launch_bounds__(256) void finish_relu_kernel(const float2* __restrict__ hp,
                                                          const float* __restrict__ bias,
                                                          float2* __restrict__ out, int n) {
    int gid = blockIdx.x * blockDim.x + threadIdx.x;
    if (gid >= n * 32) return;
    int i = gid >> 5;
    int l = gid & 31;
    float di = g_dinv[i];
    float2 a = unpack_acc(g_accu[gid], g_cntd[i]);
    float2 s = hp[gid];
    float2 bb = ((const float2*)bias)[l];
    out[gid] = make_float2(fmaxf(di * (a.x + s.x) + bb.x, 0.f),
                           fmaxf(di * (a.y + s.y) + bb.y, 0.f));
}

// ---------------- finish layer 2 fused with final FC; resets counters ----------------
__global__ __launch_bounds__(256) void finish_fc_kernel(const float2* __restrict__ hp,
                                                        const float* __restrict__ b2,
                                                        const float* __restrict__ Wfc,
                                                        const float* __restrict__ bfc,
                                                        float* __restrict__ out, int n) {
    __shared__ float Ws[64 * 11];
    __shared__ float bs[11];
    int tid = threadIdx.x;
    for (int q = tid; q < 64 * 11; q += 256) Ws[q] = Wfc[q];
    if (tid < 11) bs[tid] = bfc[tid];
    __syncthreads();

    int wid = (blockIdx.x * blockDim.x + tid) >> 5;
    int lane = tid & 31;
    if (wid >= n) return;
    const int i = wid;
    int deg = g_cntd[i];
    if (lane == 0) { g_cnts[i] = 0; g_cntd[i] = 0; }  // reset for next call
    float di = g_dinv[i];
    float2 a = unpack_acc(g_accu[(size_t)i * 32 + lane], deg);
    float2 s = hp[(size_t)i * 32 + lane];
    float2 bb = ((const float2*)b2)[lane];
    float vx = fmaxf(di * (a.x + s.x) + bb.x, 0.f);
    float vy = fmaxf(di * (a.y + s.y) + bb.y, 0.f);

    // fused FC: lane holds features 2*lane, 2*lane+1
    #pragma unroll
    for (int j = 0; j < 11; j++) {
        float p = vx * Ws[(2 * lane) * 11 + j] + vy * Ws[(2 * lane + 1) * 11 + j];
        #pragma unroll
        for (int o = 16; o; o >>= 1) p += __shfl_xor_sync(0xffffffffu, p, o);
        if (lane == j) out[(size_t)i * 11 + j] = p + bs[j];
    }
}

// ---------------- launch ----------------
extern "C" void kernel_launch(void* const* d_in, const int* in_sizes, int n_in,
                              void* d_out, int out_size) {
    const float* x   = (const float*)d_in[0];
    const void*  ei  = d_in[1];
    const float* W1  = (const float*)d_in[2];
    const float* b1  = (const float*)d_in[3];
    const float* W2  = (const float*)d_in[4];
    const float* b2  = (const float*)d_in[5];
    const float* Wfc = (const float*)d_in[6];
    const float* bfc = (const float*)d_in[7];
    float* out = (float*)d_out;

    const int n = in_sizes[0] / 256;   // 100000
    const int E = in_sizes[1] / 2;     // 1600000

    const int TB = 256;
    int nb_edge = (E + TB - 1) / TB;                 // 6250
    int nb_gemm = (n + 127) / 128;                   // 782
    int nb_push = (n * 32 + TB - 1) / TB;            // 12500 (warp per src)
    int nb_fin  = (n * 32 + TB - 1) / TB;            // 12500
    int nb_zero = (NN * 16 + TB - 1) / TB;           // 6250

    // counters zero at first call (BSS); reset by finish_fc each call.
    count2_kernel<<<nb_edge, TB>>>(ei, E);                                  // 1
    scan_kernel<<<1, 1024>>>(n);                                            // 2
    reorder_kernel<<<nb_edge, TB>>>(ei, E);                                 // 3
    gemm_dinv_kernel<256><<<nb_gemm, TB>>>(x, W1, g_h1, n);                 // 4 <-- profiled
    zero_acc_kernel<<<nb_zero, TB>>>();                                     // 5
    push_kernel<<<nb_push, TB>>>(n, (const float2*)g_h1);                   // 6
    finish_relu_kernel<<<nb_fin, TB>>>((const float2*)g_h1, b1,
                                       (float2*)g_ha, n);                   // 7
    gemm_dinv_kernel<64><<<nb_gemm, TB>>>(g_ha, W2, g_h1, n);               // 8
    zero_acc_kernel<<<nb_zero, TB>>>();                                     // 9
    push_kernel<<<nb_push, TB>>>(n, (const float2*)g_h1);                   // 10
    finish_fc_kernel<<<nb_fin, TB>>>((const float2*)g_h1, b2,
                                     Wfc, bfc, out, n);                     // 11
}